// round 2
// baseline (speedup 1.0000x reference)
#include <cuda_runtime.h>
#include <cstdint>

// EntropyCalculator: per-row histogram entropy.
//   x: [B, 64] int32, values in [0, 40)
//   out: [B, 1] float32
// H(row) = ln(64) - (1/64) * sum_v c_v * ln(c_v)

#define NT 256          // threads per block = rows per block
#define ROW_I4 16       // 64 ints = 16 int4 per row
#define TILE_STRIDE 17  // packed words per row + 1 pad (odd => conflict-free row reads)
#define NWORDS 10       // 40 vocab bins packed as 4x8-bit byte counts per word

__global__ __launch_bounds__(NT, 6) void entropy_hist_kernel(
    const int4* __restrict__ x, float* __restrict__ out, int B)
{
    __shared__ uint32_t tile[NT * TILE_STRIDE];   // byte-packed ids, 16 words/row
    __shared__ uint32_t hist[NWORDS * NT];        // per-thread byte-packed counts
    __shared__ float    lut[65];                  // lut[c] = c * ln(c) / 64

    const int tid  = threadIdx.x;
    const int row0 = blockIdx.x * NT;

    // c*ln(c)/64 LUT (65 entries; counts never exceed 64)
    if (tid <= 64) {
        lut[tid] = (tid == 0) ? 0.0f : (float)tid * logf((float)tid) * 0.015625f;
    }

    // Zero histograms (private column per thread)
    #pragma unroll
    for (int i = 0; i < NWORDS; i++) hist[i * NT + tid] = 0u;

    // Stage 256 rows with fully-coalesced int4 loads; PRMT-pack 4 ids/byte-word.
    const int rows_here = min(NT, B - row0);
    const int e_limit   = rows_here * ROW_I4;
    const int4* gp = x + (size_t)row0 * ROW_I4;
    #pragma unroll
    for (int k = 0; k < ROW_I4; k++) {
        int e = tid + k * NT;
        if (e < e_limit) {
            int4 w = __ldcs(&gp[e]);
            uint32_t t1 = __byte_perm((uint32_t)w.x, (uint32_t)w.y, 0x0040);
            uint32_t t2 = __byte_perm((uint32_t)w.z, (uint32_t)w.w, 0x0040);
            uint32_t p  = __byte_perm(t1, t2, 0x5410);
            tile[(e >> 4) * TILE_STRIDE + (e & 15)] = p;
        }
    }
    __syncthreads();

    const int row = row0 + tid;
    if (row < B) {
        // Histogram own row: 64 byte-count increments, conflict-free (bank = tid%32)
        const uint32_t* my = &tile[tid * TILE_STRIDE];
        uint32_t* ht = &hist[tid];
        #pragma unroll
        for (int j = 0; j < ROW_I4; j++) {
            uint32_t p = my[j];
            #pragma unroll
            for (int b = 0; b < 4; b++) {
                uint32_t v   = __byte_perm(p, 0u, 0x4440 + b);  // zero-extended byte b
                uint32_t add = 1u << ((v & 3u) << 3);           // byte lane within word
                ht[(v >> 2) * NT] += add;                       // private column RMW
            }
        }

        // Entropy: H = ln(64) - sum c*ln(c)/64
        float acc = 0.0f;
        #pragma unroll
        for (int i = 0; i < NWORDS; i++) {
            uint32_t w = hist[i * NT + tid];
            acc += lut[w & 0xFFu];
            acc += lut[(w >> 8) & 0xFFu];
            acc += lut[(w >> 16) & 0xFFu];
            acc += lut[w >> 24];
        }
        out[row] = 4.1588830833596718565f - acc;  // ln(64) - acc
    }
}

extern "C" void kernel_launch(void* const* d_in, const int* in_sizes, int n_in,
                              void* d_out, int out_size)
{
    const int4* x = (const int4*)d_in[0];
    float* out    = (float*)d_out;
    int B = in_sizes[0] / 64;
    int grid = (B + NT - 1) / NT;
    entropy_hist_kernel<<<grid, NT>>>(x, out, B);
}